// round 1
// baseline (speedup 1.0000x reference)
#include <cuda_runtime.h>

// NeRF volume rendering compositing.
// Inputs (metadata order):
//   d_in[0]: sigma  [B, S]    float32   (B=65536, S=512)
//   d_in[1]: dists  [B, S]    float32
//   d_in[2]: rgb    [B, S, 3] float32
//   d_in[3]: bg_col [3]       float32
// Output: rgb_map [B, 3] float32
//
// Math (faithful to reference):
//   x_i     = sigma_i * dists_i * 25
//   alpha_i = 1 - exp(-x_i)
//   T_i     = prod_{j<i} (exp(-x_j) + 1e-10)        (exclusive)
//   w_i     = alpha_i * T_i
//   out_c   = sum_i w_i * clip(rgb_ic, 0, 1) + (1 - sum_i w_i) * bg_c
//
// Early ray termination: once T < 1e-7, all remaining weights sum to < 1e-7
// (telescoping), so their contribution is below 1e-7 absolute — 4 orders of
// magnitude under the 1e-3 rel-err gate. One warp per ray; rounds of 128
// samples (4/lane, float4-coalesced); per-lane rgb loads predicated on the
// lane's starting transmittance; warp-uniform break across rounds.

#define DIST_SCALE 25.0f
#define T_THRESH   1e-7f
#define FULLMASK   0xffffffffu

__device__ __forceinline__ float clip01(float v) {
    return fminf(fmaxf(v, 0.0f), 1.0f);
}

__global__ __launch_bounds__(256, 8)
void nerf_composite_kernel(const float4* __restrict__ sigma4,
                           const float4* __restrict__ dists4,
                           const float4* __restrict__ rgb4,
                           const float*  __restrict__ bg,
                           float*        __restrict__ out,
                           int B)
{
    const int warp = (int)((blockIdx.x * (unsigned)blockDim.x + threadIdx.x) >> 5);
    const int lane = threadIdx.x & 31;
    if (warp >= B) return;

    float T_run = 1.0f;          // uniform across the warp
    float accW = 0.0f, accR = 0.0f, accG = 0.0f, accB = 0.0f;

    // S = 512 samples = 4 rounds of 128 (4 samples/lane).
    #pragma unroll 1
    for (int k = 0; k < 4; ++k) {
        const int idx = warp * 128 + k * 32 + lane;   // float4 index into sigma/dists
        const float4 sg = sigma4[idx];
        const float4 dt = dists4[idx];

        // Transmittance factors f = exp(-sigma*dist*25)
        const float f0 = __expf(-DIST_SCALE * sg.x * dt.x);
        const float f1 = __expf(-DIST_SCALE * sg.y * dt.y);
        const float f2 = __expf(-DIST_SCALE * sg.z * dt.z);
        const float f3 = __expf(-DIST_SCALE * sg.w * dt.w);

        // Local weights with local T starting at 1 (reference adds 1e-10 to 1-alpha)
        const float g0 = f0 + 1e-10f;
        const float g1 = f1 + 1e-10f;
        const float g2 = f2 + 1e-10f;
        const float g3 = f3 + 1e-10f;

        float w0 = (1.0f - f0);
        float t  = g0;
        float w1 = (1.0f - f1) * t;  t *= g1;
        float w2 = (1.0f - f2) * t;  t *= g2;
        float w3 = (1.0f - f3) * t;
        const float p = t * g3;      // product of this lane's 4 factors

        // Warp inclusive prefix product of p
        float incl = p;
        #pragma unroll
        for (int off = 1; off < 32; off <<= 1) {
            const float v = __shfl_up_sync(FULLMASK, incl, off);
            if (lane >= off) incl *= v;
        }
        float excl = __shfl_up_sync(FULLMASK, incl, 1);
        if (lane == 0) excl = 1.0f;
        const float total = __shfl_sync(FULLMASK, incl, 31);

        const float Tl = T_run * excl;   // transmittance at this lane's first sample

        // Per-lane predication: lanes whose remaining transmittance is
        // negligible skip the rgb traffic entirely (contribution < T_THRESH abs).
        if (Tl >= T_THRESH) {
            const int ridx = warp * 384 + k * 96 + lane * 3;
            const float4 q0 = rgb4[ridx + 0];
            const float4 q1 = rgb4[ridx + 1];
            const float4 q2 = rgb4[ridx + 2];

            w0 *= Tl; w1 *= Tl; w2 *= Tl; w3 *= Tl;

            accR += w0 * clip01(q0.x) + w1 * clip01(q0.w)
                  + w2 * clip01(q1.z) + w3 * clip01(q2.y);
            accG += w0 * clip01(q0.y) + w1 * clip01(q1.x)
                  + w2 * clip01(q1.w) + w3 * clip01(q2.z);
            accB += w0 * clip01(q0.z) + w1 * clip01(q1.y)
                  + w2 * clip01(q2.x) + w3 * clip01(q2.w);
            accW += w0 + w1 + w2 + w3;
        }

        T_run *= total;                  // stays warp-uniform
        if (T_run < T_THRESH) break;     // warp-uniform early exit
    }

    // Warp reduction
    #pragma unroll
    for (int off = 16; off >= 1; off >>= 1) {
        accW += __shfl_down_sync(FULLMASK, accW, off);
        accR += __shfl_down_sync(FULLMASK, accR, off);
        accG += __shfl_down_sync(FULLMASK, accG, off);
        accB += __shfl_down_sync(FULLMASK, accB, off);
    }

    if (lane == 0) {
        const float rem = 1.0f - accW;
        out[warp * 3 + 0] = accR + rem * __ldg(&bg[0]);
        out[warp * 3 + 1] = accG + rem * __ldg(&bg[1]);
        out[warp * 3 + 2] = accB + rem * __ldg(&bg[2]);
    }
}

extern "C" void kernel_launch(void* const* d_in, const int* in_sizes, int n_in,
                              void* d_out, int out_size)
{
    const float4* sigma4 = (const float4*)d_in[0];
    const float4* dists4 = (const float4*)d_in[1];
    const float4* rgb4   = (const float4*)d_in[2];
    const float*  bg     = (const float*) d_in[3];
    float*        out    = (float*)d_out;

    const int B = in_sizes[0] / 512;          // 65536 rays
    const int threads = 256;                   // 8 warps/block -> 8 rays/block
    const int blocks  = (B + 7) / 8;

    nerf_composite_kernel<<<blocks, threads>>>(sigma4, dists4, rgb4, bg, out, B);
}

// round 3
// speedup vs baseline: 1.3804x; 1.3804x over previous
#include <cuda_runtime.h>

// NeRF volume rendering compositing — round 2 retry (infra failure last round).
// Inputs (metadata order):
//   d_in[0]: sigma  [B, S]    float32   (B=65536, S=512)
//   d_in[1]: dists  [B, S]    float32
//   d_in[2]: rgb    [B, S, 3] float32
//   d_in[3]: bg_col [3]       float32
// Output: rgb_map [B, 3] float32
//
//   x_i     = sigma_i * dists_i * 25
//   alpha_i = 1 - exp(-x_i)
//   T_i     = prod_{j<i} (exp(-x_j) + 1e-10)   (exclusive transmittance)
//   w_i     = alpha_i * T_i
//   out_c   = sum_i w_i * clip(rgb_ic,0,1) + (1 - sum_i w_i) * bg_c
//
// Early termination at T < 1e-5: skipped weight mass telescopes to < 1e-5
// absolute error per channel (1e-3 rel-err gate; observed rel_err ~ 2.8*tau
// -> ~3e-5). One warp per ray, rounds of 64 samples (2/lane, float2 loads).
// Per-lane rgb loads predicated on the lane's starting transmittance;
// warp-uniform break between rounds. ~99.5% of rays finish in round 0;
// predicted DRAM traffic ~71 MB.

#define DIST_SCALE 25.0f
#define T_THRESH   1e-5f
#define FULLMASK   0xffffffffu

__device__ __forceinline__ float clip01(float v) {
    return fminf(fmaxf(v, 0.0f), 1.0f);
}

__global__ __launch_bounds__(256, 8)
void nerf_composite_kernel(const float2* __restrict__ sigma2,
                           const float2* __restrict__ dists2,
                           const float2* __restrict__ rgb2,
                           const float*  __restrict__ bg,
                           float*        __restrict__ out,
                           int B)
{
    const int warp = (int)((blockIdx.x * (unsigned)blockDim.x + threadIdx.x) >> 5);
    const int lane = threadIdx.x & 31;
    if (warp >= B) return;

    float T_run = 1.0f;          // warp-uniform running transmittance
    float accW = 0.0f, accR = 0.0f, accG = 0.0f, accB = 0.0f;

    // S = 512 samples = 8 rounds of 64 (2 samples/lane).
    #pragma unroll 1
    for (int k = 0; k < 8; ++k) {
        const int idx = warp * 256 + k * 32 + lane;   // float2 index into sigma/dists
        const float2 sg = __ldcs(&sigma2[idx]);
        const float2 dt = __ldcs(&dists2[idx]);

        // Transmittance factors f = exp(-sigma*dist*25)
        const float f0 = __expf(-DIST_SCALE * sg.x * dt.x);
        const float f1 = __expf(-DIST_SCALE * sg.y * dt.y);
        const float g0 = f0 + 1e-10f;
        const float g1 = f1 + 1e-10f;

        float w0 = (1.0f - f0);
        float w1 = (1.0f - f1) * g0;
        const float p = g0 * g1;     // product of this lane's 2 factors

        // Warp inclusive prefix product of p
        float incl = p;
        #pragma unroll
        for (int off = 1; off < 32; off <<= 1) {
            const float v = __shfl_up_sync(FULLMASK, incl, off);
            if (lane >= off) incl *= v;
        }
        float excl = __shfl_up_sync(FULLMASK, incl, 1);
        if (lane == 0) excl = 1.0f;
        const float total = __shfl_sync(FULLMASK, incl, 31);

        const float Tl = T_run * excl;   // transmittance at this lane's first sample

        // Lanes with negligible remaining transmittance skip rgb traffic.
        if (Tl >= T_THRESH) {
            // rgb floats per lane: [r0,g0,b0,r1,g1,b1] at float2 index:
            const int ridx = warp * 768 + k * 96 + lane * 3;
            const float2 q0 = __ldcs(&rgb2[ridx + 0]);   // r0 g0
            const float2 q1 = __ldcs(&rgb2[ridx + 1]);   // b0 r1
            const float2 q2 = __ldcs(&rgb2[ridx + 2]);   // g1 b1

            w0 *= Tl; w1 *= Tl;

            accR += w0 * clip01(q0.x) + w1 * clip01(q1.y);
            accG += w0 * clip01(q0.y) + w1 * clip01(q2.x);
            accB += w0 * clip01(q1.x) + w1 * clip01(q2.y);
            accW += w0 + w1;
        }

        T_run *= total;                  // stays warp-uniform
        if (T_run < T_THRESH) break;     // warp-uniform early exit
    }

    // Warp reduction
    #pragma unroll
    for (int off = 16; off >= 1; off >>= 1) {
        accW += __shfl_down_sync(FULLMASK, accW, off);
        accR += __shfl_down_sync(FULLMASK, accR, off);
        accG += __shfl_down_sync(FULLMASK, accG, off);
        accB += __shfl_down_sync(FULLMASK, accB, off);
    }

    if (lane == 0) {
        const float rem = 1.0f - accW;
        out[warp * 3 + 0] = accR + rem * __ldg(&bg[0]);
        out[warp * 3 + 1] = accG + rem * __ldg(&bg[1]);
        out[warp * 3 + 2] = accB + rem * __ldg(&bg[2]);
    }
}

extern "C" void kernel_launch(void* const* d_in, const int* in_sizes, int n_in,
                              void* d_out, int out_size)
{
    const float2* sigma2 = (const float2*)d_in[0];
    const float2* dists2 = (const float2*)d_in[1];
    const float2* rgb2   = (const float2*)d_in[2];
    const float*  bg     = (const float*) d_in[3];
    float*        out    = (float*)d_out;

    const int B = in_sizes[0] / 512;          // 65536 rays
    const int threads = 256;                   // 8 warps/block -> 8 rays/block
    const int blocks  = (B + 7) / 8;

    nerf_composite_kernel<<<blocks, threads>>>(sigma2, dists2, rgb2, bg, out, B);
}

// round 4
// speedup vs baseline: 1.8549x; 1.3437x over previous
#include <cuda_runtime.h>

// NeRF volume rendering compositing — round 4.
// Inputs (metadata order):
//   d_in[0]: sigma  [B, S]    float32   (B=65536, S=512)
//   d_in[1]: dists  [B, S]    float32
//   d_in[2]: rgb    [B, S, 3] float32
//   d_in[3]: bg_col [3]       float32
// Output: rgb_map [B, 3] float32
//
//   x_i = sigma_i*dists_i*25; alpha = 1-exp(-x); T = excl cumprod(exp(-x)+1e-10)
//   w = alpha*T; out_c = sum w*clip(rgb,0,1) + (1-sum w)*bg_c
//
// Two rays per warp: each 16-lane segment owns one ray. Rounds of 64 samples
// (4/lane) with float4-coalesced sigma/dists loads (restores R1's MLP /
// bandwidth) while keeping the 64-sample round-0 traffic of R3. Early
// termination at T < 3e-5 (worst observed error scaling 2.8*tau -> <1e-4,
// 12x under the 1e-3 gate). Per-lane rgb loads predicated on the lane's
// starting transmittance. ~All rays terminate in round 0 at this tau.

#define DIST_SCALE 25.0f
#define T_THRESH   3e-5f
#define FULLMASK   0xffffffffu
#define SEGW       16

__device__ __forceinline__ float clip01(float v) {
    return fminf(fmaxf(v, 0.0f), 1.0f);
}

__global__ __launch_bounds__(256, 8)
void nerf_composite_kernel(const float4* __restrict__ sigma4,
                           const float4* __restrict__ dists4,
                           const float4* __restrict__ rgb4,
                           const float*  __restrict__ bg,
                           float*        __restrict__ out,
                           int B)
{
    const int warp  = (int)((blockIdx.x * (unsigned)blockDim.x + threadIdx.x) >> 5);
    const int lane  = threadIdx.x & 31;
    const int slane = lane & (SEGW - 1);        // lane within 16-lane segment
    const int ray   = warp * 2 + (lane >> 4);   // one ray per half-warp
    if (ray >= B) return;

    float T_run = 1.0f;          // uniform within the segment
    float accW = 0.0f, accR = 0.0f, accG = 0.0f, accB = 0.0f;

    // S = 512 samples = 8 rounds of 64 (4 samples/lane, float4 loads).
    #pragma unroll 1
    for (int k = 0; k < 8; ++k) {
        const int idx = ray * 128 + k * 16 + slane;   // float4 index into sigma/dists
        const float4 sg = __ldcs(&sigma4[idx]);
        const float4 dt = __ldcs(&dists4[idx]);

        // Transmittance factors f = exp(-sigma*dist*25)
        const float f0 = __expf(-DIST_SCALE * sg.x * dt.x);
        const float f1 = __expf(-DIST_SCALE * sg.y * dt.y);
        const float f2 = __expf(-DIST_SCALE * sg.z * dt.z);
        const float f3 = __expf(-DIST_SCALE * sg.w * dt.w);

        const float g0 = f0 + 1e-10f;
        const float g1 = f1 + 1e-10f;
        const float g2 = f2 + 1e-10f;
        const float g3 = f3 + 1e-10f;

        float w0 = (1.0f - f0);
        float t  = g0;
        float w1 = (1.0f - f1) * t;  t *= g1;
        float w2 = (1.0f - f2) * t;  t *= g2;
        float w3 = (1.0f - f3) * t;
        const float p = t * g3;      // product of this lane's 4 factors

        // Segment (width-16) inclusive prefix product of p
        float incl = p;
        #pragma unroll
        for (int off = 1; off < SEGW; off <<= 1) {
            const float v = __shfl_up_sync(FULLMASK, incl, off, SEGW);
            if (slane >= off) incl *= v;
        }
        float excl = __shfl_up_sync(FULLMASK, incl, 1, SEGW);
        if (slane == 0) excl = 1.0f;
        const float total = __shfl_sync(FULLMASK, incl, SEGW - 1, SEGW);

        const float Tl = T_run * excl;   // transmittance at this lane's first sample

        // Lanes with negligible remaining transmittance skip rgb traffic.
        if (Tl >= T_THRESH) {
            const int ridx = ray * 384 + k * 48 + slane * 3;   // float4 index into rgb
            const float4 q0 = __ldcs(&rgb4[ridx + 0]);
            const float4 q1 = __ldcs(&rgb4[ridx + 1]);
            const float4 q2 = __ldcs(&rgb4[ridx + 2]);

            w0 *= Tl; w1 *= Tl; w2 *= Tl; w3 *= Tl;

            accR += w0 * clip01(q0.x) + w1 * clip01(q0.w)
                  + w2 * clip01(q1.z) + w3 * clip01(q2.y);
            accG += w0 * clip01(q0.y) + w1 * clip01(q1.x)
                  + w2 * clip01(q1.w) + w3 * clip01(q2.z);
            accB += w0 * clip01(q0.z) + w1 * clip01(q1.y)
                  + w2 * clip01(q2.x) + w3 * clip01(q2.w);
            accW += w0 + w1 + w2 + w3;
        }

        T_run *= total;                          // stays segment-uniform
        const bool done = (T_run < T_THRESH);
        if (__all_sync(FULLMASK, done)) break;   // warp-uniform early exit
        // If only one segment is done, its lanes keep looping but Tl < thresh
        // suppresses all rgb traffic and accumulation — correctness unaffected.
    }

    // Segment (width-16) reduction
    #pragma unroll
    for (int off = SEGW / 2; off >= 1; off >>= 1) {
        accW += __shfl_down_sync(FULLMASK, accW, off, SEGW);
        accR += __shfl_down_sync(FULLMASK, accR, off, SEGW);
        accG += __shfl_down_sync(FULLMASK, accG, off, SEGW);
        accB += __shfl_down_sync(FULLMASK, accB, off, SEGW);
    }

    if (slane == 0) {
        const float rem = 1.0f - accW;
        out[ray * 3 + 0] = accR + rem * __ldg(&bg[0]);
        out[ray * 3 + 1] = accG + rem * __ldg(&bg[1]);
        out[ray * 3 + 2] = accB + rem * __ldg(&bg[2]);
    }
}

extern "C" void kernel_launch(void* const* d_in, const int* in_sizes, int n_in,
                              void* d_out, int out_size)
{
    const float4* sigma4 = (const float4*)d_in[0];
    const float4* dists4 = (const float4*)d_in[1];
    const float4* rgb4   = (const float4*)d_in[2];
    const float*  bg     = (const float*) d_in[3];
    float*        out    = (float*)d_out;

    const int B = in_sizes[0] / 512;           // 65536 rays
    const int threads = 256;                    // 8 warps/block -> 16 rays/block
    const int blocks  = (B + 15) / 16;

    nerf_composite_kernel<<<blocks, threads>>>(sigma4, dists4, rgb4, bg, out, B);
}